// round 3
// baseline (speedup 1.0000x reference)
#include <cuda_runtime.h>
#include <cuda_bf16.h>

#define DD 16
#define LL 6
#define KK 64

typedef unsigned long long u64;

// Scratch: normalized mus in [l][k][d] layout (pair-packed), duplicated-pair
// alpha constants, per-layer recurrence weights.
__device__ float4 g_mu[LL * KK * (DD / 4)];
__device__ u64    g_c2d[LL * KK];   // (c2, c2) duplicated for f32x2 use
__device__ float  g_wv[LL];

#define C1_        (-7.2134752044448169f)   /* -5 * log2(e)      */
#define C2SCALE_   (-14.426950408889634f)   /* -10 * log2(e)     */
#define PI_        3.14159265358979323846f
#define LN2_TENTH  0.069314718055994531f    /* 0.1 * ln(2)       */
#define CLIP_      0.99999994f              /* fp32(1.0 - 1e-7)  */

__global__ void prep_kernel(const float* __restrict__ mus,
                            const float* __restrict__ alphas,
                            const float* __restrict__ ws) {
    int tid = threadIdx.x;
    if (tid < LL) {
        float w = ws[tid];
        g_wv[tid] = expf(-w * w);
    }
    if (tid >= LL * KK) return;
    int l = tid >> 6;
    int k = tid & 63;
    const float* m = mus + l * DD * KK + k;   // [L, D, K] layout
    float v[DD];
    float s = 0.f;
#pragma unroll
    for (int d = 0; d < DD; d++) {
        v[d] = m[d * KK];
        s += v[d] * v[d];
    }
    float inv = 1.0f / sqrtf(s);
    float* dst = reinterpret_cast<float*>(&g_mu[tid * 4]);
#pragma unroll
    for (int d = 0; d < DD; d++) dst[d] = v[d] * inv;
    float c2 = C2SCALE_ * alphas[tid];
    unsigned int bits = __float_as_uint(c2);
    g_c2d[tid] = ((u64)bits << 32) | (u64)bits;
}

// ---------- fast scalar transcendentals ----------
__device__ __forceinline__ float fast_sqrt(float x) {
    float r; asm("sqrt.approx.f32 %0, %1;" : "=f"(r) : "f"(x)); return r;
}
__device__ __forceinline__ float fast_ex2(float x) {
    float r; asm("ex2.approx.f32 %0, %1;" : "=f"(r) : "f"(x)); return r;
}
__device__ __forceinline__ float fast_lg2(float x) {
    float r; asm("lg2.approx.f32 %0, %1;" : "=f"(r) : "f"(x)); return r;
}

// ---------- packed f32x2 ops ----------
__device__ __forceinline__ u64 fma2(u64 a, u64 b, u64 c) {
    u64 d; asm("fma.rn.f32x2 %0, %1, %2, %3;" : "=l"(d) : "l"(a), "l"(b), "l"(c)); return d;
}
__device__ __forceinline__ u64 mul2(u64 a, u64 b) {
    u64 d; asm("mul.rn.f32x2 %0, %1, %2;" : "=l"(d) : "l"(a), "l"(b)); return d;
}
__device__ __forceinline__ u64 add2(u64 a, u64 b) {
    u64 d; asm("add.rn.f32x2 %0, %1, %2;" : "=l"(d) : "l"(a), "l"(b)); return d;
}
__device__ __forceinline__ u64 pack2(float lo, float hi) {
    u64 d; asm("mov.b64 %0, {%1, %2};" : "=l"(d) : "f"(lo), "f"(hi)); return d;
}
__device__ __forceinline__ void unpack2(u64 v, float& lo, float& hi) {
    asm("mov.b64 {%0, %1}, %2;" : "=f"(lo), "=f"(hi) : "l"(v));
}

// packed dot of one x (8 f32 pairs) with one mu row (8 f32 pairs in 4 ulonglong2)
__device__ __forceinline__ float dot16(const u64* xp,
                                       ulonglong2 m0, ulonglong2 m1,
                                       ulonglong2 m2, ulonglong2 m3) {
    u64 a = mul2(xp[0], m0.x);
    u64 b = mul2(xp[1], m0.y);
    a = fma2(xp[2], m1.x, a);
    b = fma2(xp[3], m1.y, b);
    a = fma2(xp[4], m2.x, a);
    b = fma2(xp[5], m2.y, b);
    a = fma2(xp[6], m3.x, a);
    b = fma2(xp[7], m3.y, b);
    u64 s = add2(a, b);
    float lo, hi;
    unpack2(s, lo, hi);
    return lo + hi;
}

__global__ __launch_bounds__(256) void main_kernel(const float* __restrict__ xs,
                                                   float* __restrict__ out,
                                                   int n_total) {
    __shared__ ulonglong2 s_mu[LL * KK * 4];   // 24 KB
    __shared__ u64        s_c2d[LL * KK];      // 3 KB (duplicated pairs)
    __shared__ float      s_wv[LL];

    int tid = threadIdx.x;
    {
        const ulonglong2* gm = reinterpret_cast<const ulonglong2*>(g_mu);
        for (int i = tid; i < LL * KK * 4; i += 256) s_mu[i] = gm[i];
        for (int i = tid; i < LL * KK; i += 256) s_c2d[i] = g_c2d[i];
        if (tid < LL) s_wv[tid] = g_wv[tid];
    }
    __syncthreads();

    // two points per thread: 2*gid and 2*gid+1
    int gid = blockIdx.x * 256 + tid;
    int nA = 2 * gid;
    if (nA >= n_total) return;
    int nB = nA + 1;
    bool hasB = (nB < n_total);

    u64 xa[8], xb[8];
    {
        const ulonglong2* xv = reinterpret_cast<const ulonglong2*>(xs + (size_t)nA * DD);
        ulonglong2 v0 = xv[0], v1 = xv[1], v2 = xv[2], v3 = xv[3];
        xa[0] = v0.x; xa[1] = v0.y; xa[2] = v1.x; xa[3] = v1.y;
        xa[4] = v2.x; xa[5] = v2.y; xa[6] = v3.x; xa[7] = v3.y;
        const ulonglong2* xw = reinterpret_cast<const ulonglong2*>(
            xs + (size_t)(hasB ? nB : nA) * DD);
        ulonglong2 w0 = xw[0], w1 = xw[1], w2 = xw[2], w3 = xw[3];
        xb[0] = w0.x; xb[1] = w0.y; xb[2] = w1.x; xb[3] = w1.y;
        xb[4] = w2.x; xb[5] = w2.y; xb[6] = w3.x; xb[7] = w3.y;
    }

    // packed acos minimax constants (duplicated lanes)
    const u64 P7 = pack2(-0.0012624911f, -0.0012624911f);
    const u64 P6 = pack2( 0.0066700901f,  0.0066700901f);
    const u64 P5 = pack2(-0.0170881256f, -0.0170881256f);
    const u64 P4 = pack2( 0.0308918810f,  0.0308918810f);
    const u64 P3 = pack2(-0.0501743046f, -0.0501743046f);
    const u64 P2 = pack2( 0.0889789874f,  0.0889789874f);
    const u64 P1 = pack2(-0.2145988016f, -0.2145988016f);
    const u64 P0 = pack2( 1.5707963050f,  1.5707963050f);
    const u64 C1P = pack2(C1_, C1_);

    float FA = 0.f, FB = 0.f;
#pragma unroll 1
    for (int l = 0; l < LL; l++) {
        float sumA = 0.f, sumB = 0.f;
        const ulonglong2* mbase = s_mu + l * KK * 4;
        const u64*        cbase = s_c2d + l * KK;
#pragma unroll 4
        for (int k = 0; k < KK; k++) {
            ulonglong2 m0 = mbase[k * 4 + 0];
            ulonglong2 m1 = mbase[k * 4 + 1];
            ulonglong2 m2 = mbase[k * 4 + 2];
            ulonglong2 m3 = mbase[k * 4 + 3];

            float dotA = dot16(xa, m0, m1, m2, m3);
            float dotB = dot16(xb, m0, m1, m2, m3);

            float aA = fminf(fabsf(dotA), CLIP_);
            float aB = fminf(fabsf(dotB), CLIP_);

            // packed acos polynomial across the point pair
            u64 pa = pack2(aA, aB);
            u64 p = fma2(P7, pa, P6);
            p = fma2(p, pa, P5);
            p = fma2(p, pa, P4);
            p = fma2(p, pa, P3);
            p = fma2(p, pa, P2);
            p = fma2(p, pa, P1);
            p = fma2(p, pa, P0);
            float pA, pB;
            unpack2(p, pA, pB);

            float dpA = fast_sqrt(1.0f - aA) * pA;
            float dpB = fast_sqrt(1.0f - aB) * pB;
            float distA = (dotA < 0.f) ? (PI_ - dpA) : dpA;
            float distB = (dotB < 0.f) ? (PI_ - dpB) : dpB;

            // packed: arg = C1*dist^2 + c2   (c2 duplicated pair from smem)
            u64 dd = pack2(distA, distB);
            u64 arg = fma2(mul2(dd, dd), C1P, cbase[k]);
            float argA, argB;
            unpack2(arg, argA, argB);
            sumA += fast_ex2(argA);
            sumB += fast_ex2(argB);
        }
        float w = s_wv[l];
        float mcA = LN2_TENTH * fast_lg2(sumA);
        float mcB = LN2_TENTH * fast_lg2(sumB);
        FA = fmaf(w, fmaxf(FA, 0.f), (1.0f - w) * mcA);
        FB = fmaf(w, fmaxf(FB, 0.f), (1.0f - w) * mcB);
    }

    // smooth min(F, 0): 0.1 * log(1 + exp(-10F))
    float rA = 0.1f * log1pf(fast_ex2(C2SCALE_ * FA));
    float rB = 0.1f * log1pf(fast_ex2(C2SCALE_ * FB));
    out[nA] = rA;
    if (hasB) out[nB] = rB;
}

extern "C" void kernel_launch(void* const* d_in, const int* in_sizes, int n_in,
                              void* d_out, int out_size) {
    const float* xs     = (const float*)d_in[0];
    const float* mus    = (const float*)d_in[1];
    const float* alphas = (const float*)d_in[2];
    const float* ws     = (const float*)d_in[3];
    float* out = (float*)d_out;

    int n_total = in_sizes[0] / DD;
    int n_pairs = (n_total + 1) / 2;

    prep_kernel<<<1, LL * KK>>>(mus, alphas, ws);
    int blocks = (n_pairs + 255) / 256;
    main_kernel<<<blocks, 256>>>(xs, out, n_total);
}

// round 4
// speedup vs baseline: 1.0907x; 1.0907x over previous
#include <cuda_runtime.h>
#include <cuda_bf16.h>

#define DD 16
#define LL 6
#define KK 64

#define NUM_SMS   148
#define CTAS_PER_SM 5
#define BLOCK     256
#define GRID_MAIN (NUM_SMS * CTAS_PER_SM)

typedef unsigned long long u64;

// Scratch: normalized mus in [l][k][d] layout (pair-packed), duplicated-pair
// alpha constants, per-layer recurrence weights.
__device__ float4 g_mu[LL * KK * (DD / 4)];
__device__ u64    g_c2d[LL * KK];   // (c2, c2) duplicated for f32x2 use
__device__ float  g_wv[LL];

#define C1_        (-7.2134752044448169f)   /* -5 * log2(e)      */
#define C2SCALE_   (-14.426950408889634f)   /* -10 * log2(e)     */
#define PI_        3.14159265358979323846f
#define LN2_TENTH  0.069314718055994531f    /* 0.1 * ln(2)       */
#define CLIP_      0.99999994f              /* fp32(1.0 - 1e-7)  */

__global__ void prep_kernel(const float* __restrict__ mus,
                            const float* __restrict__ alphas,
                            const float* __restrict__ ws) {
    int tid = threadIdx.x;
    if (tid < LL) {
        float w = ws[tid];
        g_wv[tid] = expf(-w * w);
    }
    if (tid >= LL * KK) return;
    int l = tid >> 6;
    int k = tid & 63;
    const float* m = mus + l * DD * KK + k;   // [L, D, K] layout
    float v[DD];
    float s = 0.f;
#pragma unroll
    for (int d = 0; d < DD; d++) {
        v[d] = m[d * KK];
        s += v[d] * v[d];
    }
    float inv = 1.0f / sqrtf(s);
    float* dst = reinterpret_cast<float*>(&g_mu[tid * 4]);
#pragma unroll
    for (int d = 0; d < DD; d++) dst[d] = v[d] * inv;
    float c2 = C2SCALE_ * alphas[tid];
    unsigned int bits = __float_as_uint(c2);
    g_c2d[tid] = ((u64)bits << 32) | (u64)bits;
}

// ---------- fast scalar transcendentals ----------
__device__ __forceinline__ float fast_sqrt(float x) {
    float r; asm("sqrt.approx.f32 %0, %1;" : "=f"(r) : "f"(x)); return r;
}
__device__ __forceinline__ float fast_ex2(float x) {
    float r; asm("ex2.approx.f32 %0, %1;" : "=f"(r) : "f"(x)); return r;
}
__device__ __forceinline__ float fast_lg2(float x) {
    float r; asm("lg2.approx.f32 %0, %1;" : "=f"(r) : "f"(x)); return r;
}

// ---------- packed f32x2 ops ----------
__device__ __forceinline__ u64 fma2(u64 a, u64 b, u64 c) {
    u64 d; asm("fma.rn.f32x2 %0, %1, %2, %3;" : "=l"(d) : "l"(a), "l"(b), "l"(c)); return d;
}
__device__ __forceinline__ u64 mul2(u64 a, u64 b) {
    u64 d; asm("mul.rn.f32x2 %0, %1, %2;" : "=l"(d) : "l"(a), "l"(b)); return d;
}
__device__ __forceinline__ u64 add2(u64 a, u64 b) {
    u64 d; asm("add.rn.f32x2 %0, %1, %2;" : "=l"(d) : "l"(a), "l"(b)); return d;
}
__device__ __forceinline__ u64 pack2(float lo, float hi) {
    u64 d; asm("mov.b64 %0, {%1, %2};" : "=l"(d) : "f"(lo), "f"(hi)); return d;
}
__device__ __forceinline__ void unpack2(u64 v, float& lo, float& hi) {
    asm("mov.b64 {%0, %1}, %2;" : "=f"(lo), "=f"(hi) : "l"(v));
}

// packed dot of one x (8 f32 pairs) with one mu row (8 f32 pairs in 4 ulonglong2)
__device__ __forceinline__ float dot16(const u64* xp,
                                       ulonglong2 m0, ulonglong2 m1,
                                       ulonglong2 m2, ulonglong2 m3) {
    u64 a = mul2(xp[0], m0.x);
    u64 b = mul2(xp[1], m0.y);
    a = fma2(xp[2], m1.x, a);
    b = fma2(xp[3], m1.y, b);
    a = fma2(xp[4], m2.x, a);
    b = fma2(xp[5], m2.y, b);
    a = fma2(xp[6], m3.x, a);
    b = fma2(xp[7], m3.y, b);
    u64 s = add2(a, b);
    float lo, hi;
    unpack2(s, lo, hi);
    return lo + hi;
}

__global__ __launch_bounds__(BLOCK, CTAS_PER_SM)
void main_kernel(const float* __restrict__ xs,
                 float* __restrict__ out,
                 int n_total) {
    __shared__ ulonglong2 s_mu[LL * KK * 4];   // 24 KB
    __shared__ float2     s_c2[LL * KK / 2];   // 1.5 KB (pairs of distinct c2 kept packed)
    __shared__ float      s_wv[LL];

    int tid = threadIdx.x;
    {
        const ulonglong2* gm = reinterpret_cast<const ulonglong2*>(g_mu);
        for (int i = tid; i < LL * KK * 4; i += BLOCK) s_mu[i] = gm[i];
        // store c2 as adjacent-k pairs (float2) for the k-pair loop
        const u64* gc = g_c2d;
        for (int i = tid; i < LL * KK / 2; i += BLOCK) {
            float lo, hi, dummy;
            unpack2(gc[2 * i], lo, dummy);
            unpack2(gc[2 * i + 1], hi, dummy);
            s_c2[i] = make_float2(lo, hi);
        }
        if (tid < LL) s_wv[tid] = g_wv[tid];
    }
    __syncthreads();

    // packed acos minimax constants (duplicated lanes), hoisted out of the point loop
    const u64 P7 = pack2(-0.0012624911f, -0.0012624911f);
    const u64 P6 = pack2( 0.0066700901f,  0.0066700901f);
    const u64 P5 = pack2(-0.0170881256f, -0.0170881256f);
    const u64 P4 = pack2( 0.0308918810f,  0.0308918810f);
    const u64 P3 = pack2(-0.0501743046f, -0.0501743046f);
    const u64 P2 = pack2( 0.0889789874f,  0.0889789874f);
    const u64 P1 = pack2(-0.2145988016f, -0.2145988016f);
    const u64 P0 = pack2( 1.5707963050f,  1.5707963050f);

    const int stride = GRID_MAIN * BLOCK;

    // persistent grid-stride loop: single fully-resident wave, no CTA quantization
    for (int n = blockIdx.x * BLOCK + tid; n < n_total; n += stride) {
        u64 xp[8];
        {
            const ulonglong2* xv = reinterpret_cast<const ulonglong2*>(xs + (size_t)n * DD);
            ulonglong2 v0 = xv[0], v1 = xv[1], v2 = xv[2], v3 = xv[3];
            xp[0] = v0.x; xp[1] = v0.y; xp[2] = v1.x; xp[3] = v1.y;
            xp[4] = v2.x; xp[5] = v2.y; xp[6] = v3.x; xp[7] = v3.y;
        }

        float F = 0.f;
#pragma unroll 1
        for (int l = 0; l < LL; l++) {
            float sum0 = 0.f, sum1 = 0.f;
            const ulonglong2* mbase = s_mu + l * KK * 4;
            const float2*     cbase = s_c2 + l * (KK / 2);
#pragma unroll 4
            for (int kp = 0; kp < KK / 2; kp++) {
                const ulonglong2* m0p = mbase + (2 * kp) * 4;
                const ulonglong2* m1p = mbase + (2 * kp + 1) * 4;
                float dot0 = dot16(xp, m0p[0], m0p[1], m0p[2], m0p[3]);
                float dot1 = dot16(xp, m1p[0], m1p[1], m1p[2], m1p[3]);

                float a0 = fminf(fabsf(dot0), CLIP_);
                float a1 = fminf(fabsf(dot1), CLIP_);

                // packed acos polynomial across the k-pair
                u64 pa = pack2(a0, a1);
                u64 p = fma2(P7, pa, P6);
                p = fma2(p, pa, P5);
                p = fma2(p, pa, P4);
                p = fma2(p, pa, P3);
                p = fma2(p, pa, P2);
                p = fma2(p, pa, P1);
                p = fma2(p, pa, P0);
                float p0, p1;
                unpack2(p, p0, p1);

                float dp0 = fast_sqrt(1.0f - a0) * p0;
                float dp1 = fast_sqrt(1.0f - a1) * p1;
                float dist0 = (dot0 < 0.f) ? (PI_ - dp0) : dp0;
                float dist1 = (dot1 < 0.f) ? (PI_ - dp1) : dp1;

                float2 c2 = cbase[kp];
                float arg0 = fmaf(dist0 * dist0, C1_, c2.x);
                float arg1 = fmaf(dist1 * dist1, C1_, c2.y);
                sum0 += fast_ex2(arg0);
                sum1 += fast_ex2(arg1);
            }
            float mincost = LN2_TENTH * fast_lg2(sum0 + sum1);
            float w = s_wv[l];
            F = fmaf(w, fmaxf(F, 0.f), (1.0f - w) * mincost);
        }

        // smooth min(F, 0): 0.1 * log(1 + exp(-10F))
        float s = fast_ex2(C2SCALE_ * F);
        out[n] = 0.1f * log1pf(s);
    }
}

extern "C" void kernel_launch(void* const* d_in, const int* in_sizes, int n_in,
                              void* d_out, int out_size) {
    const float* xs     = (const float*)d_in[0];
    const float* mus    = (const float*)d_in[1];
    const float* alphas = (const float*)d_in[2];
    const float* ws     = (const float*)d_in[3];
    float* out = (float*)d_out;

    int n_total = in_sizes[0] / DD;

    prep_kernel<<<1, LL * KK>>>(mus, alphas, ws);
    main_kernel<<<GRID_MAIN, BLOCK>>>(xs, out, n_total);
}